// round 2
// baseline (speedup 1.0000x reference)
#include <cuda_runtime.h>
#include <cstdint>

#define BATCH 8
#define CC    64
#define CQ    8
#define NN_   4096
#define TM    128
#define TN    64
#define THREADS 256
#define WROW  (TN + 1)   // 65: pad so STS of w is conflict-free

typedef unsigned long long ull;

// Scratch (device globals; no allocation allowed)
__device__ float g_fT[(size_t)BATCH * CQ * NN_];  // [B][8][N], pre-scaled by log2e
__device__ float g_g [(size_t)BATCH * NN_ * CQ];  // [B][N][8]
__device__ float g_h [(size_t)BATCH * NN_ * CC];  // [B][N][64]

// ---- packed f32x2 helpers ----
__device__ __forceinline__ ull pack2(float a, float b) {
    ull r; asm("mov.b64 %0, {%1, %2};" : "=l"(r) : "f"(a), "f"(b)); return r;
}
__device__ __forceinline__ void unpack2(ull v, float& a, float& b) {
    asm("mov.b64 {%0, %1}, %2;" : "=f"(a), "=f"(b) : "l"(v));
}
__device__ __forceinline__ ull ffma2(ull a, ull b, ull c) {
    ull d; asm("fma.rn.f32x2 %0, %1, %2, %3;" : "=l"(d) : "l"(a), "l"(b), "l"(c)); return d;
}
__device__ __forceinline__ ull add2(ull a, ull b) {
    ull d; asm("add.rn.f32x2 %0, %1, %2;" : "=l"(d) : "l"(a), "l"(b)); return d;
}
__device__ __forceinline__ ull mul2(ull a, ull b) {
    ull d; asm("mul.rn.f32x2 %0, %1, %2;" : "=l"(d) : "l"(a), "l"(b)); return d;
}

// ============================================================================
// Kernel 1: 1x1-conv projections.
//   x:[B,64,N] -> f^T (scaled by log2e): [B,8,N], g: [B,N,8], h: [B,N,64]
// ============================================================================
__global__ __launch_bounds__(128) void proj_kernel(
    const float* __restrict__ x,
    const float* __restrict__ Wq, const float* __restrict__ bq,
    const float* __restrict__ Wk, const float* __restrict__ bk,
    const float* __restrict__ Wv, const float* __restrict__ bv)
{
    __shared__ float sWq[CQ * CC], sWk[CQ * CC], sWv[CC * CC];
    __shared__ float sbq[CQ], sbk[CQ], sbv[CC];
    int t = threadIdx.x;
    for (int i = t; i < CQ * CC; i += 128) { sWq[i] = Wq[i]; sWk[i] = Wk[i]; }
    for (int i = t; i < CC * CC; i += 128) sWv[i] = Wv[i];
    if (t < CQ) { sbq[t] = bq[t]; sbk[t] = bk[t]; }
    if (t < CC) sbv[t] = bv[t];
    __syncthreads();

    int b = blockIdx.x / (NN_ / 128);
    int n = (blockIdx.x % (NN_ / 128)) * 128 + t;

    float xv[CC];
    const float* xb = x + ((size_t)b * CC) * NN_ + n;
    #pragma unroll
    for (int c = 0; c < CC; c++) xv[c] = xb[(size_t)c * NN_];

    const float LOG2E = 1.4426950408889634f;
    size_t base = (size_t)b * NN_ + n;

    #pragma unroll 2
    for (int d = 0; d < CQ; d++) {
        float af = sbq[d], ag = sbk[d];
        #pragma unroll
        for (int c = 0; c < CC; c++) {
            af = fmaf(sWq[d * CC + c], xv[c], af);
            ag = fmaf(sWk[d * CC + c], xv[c], ag);
        }
        g_fT[((size_t)b * CQ + d) * NN_ + n] = af * LOG2E;   // key, pre-scaled
        g_g[base * CQ + d] = ag;                              // query
    }
    #pragma unroll 4
    for (int o = 0; o < CC; o++) {
        float a = sbv[o];
        #pragma unroll
        for (int c = 0; c < CC; c++) a = fmaf(sWv[o * CC + c], xv[c], a);
        g_h[base * CC + o] = a;
    }
}

// ============================================================================
// Kernel 2: fused attention, two-stage tiles, no max pass, polynomial exp2.
//   Block: 128 m x full n sweep in 64-n tiles. 256 threads.
//   Stage A: w[m][n] = 2^(q_m . fT_n) into smem (f32x2 scores + poly exp2)
//   Stage B: acc[4m][8c] += w * h  (all fma.rn.f32x2)
// ============================================================================
__global__ __launch_bounds__(THREADS, 2) void attn_kernel(
    const float* __restrict__ x,
    const float* __restrict__ gamma,
    float* __restrict__ out)
{
    extern __shared__ float smem[];
    float* w_s = smem;                     // [128][65]
    float* h_s = w_s + TM * WROW;          // [64][64]
    float* f_s = h_s + TN * CC;            // [8][64]
    float* l_s = f_s + CQ * TN;            // [128]

    int t = threadIdx.x;
    int b  = blockIdx.x >> 5;              // 32 m-tiles per batch
    int mt = (blockIdx.x & 31) * TM;

    // stage-A identity: 2 threads per m, split n range in halves
    int mloc = t & 127;
    int nh   = (t >> 7) * 32;
    // stage-B identity: 4m x 8c register tile
    int tc  = t & 7;
    int tmg = t >> 3;

    // q for my m (stage A), packed as (q,q)
    ull qp[CQ];
    {
        const float* qg = g_g + ((size_t)b * NN_ + mt + mloc) * CQ;
        float4 q0 = *(const float4*)qg;
        float4 q1 = *(const float4*)(qg + 4);
        qp[0] = pack2(q0.x, q0.x); qp[1] = pack2(q0.y, q0.y);
        qp[2] = pack2(q0.z, q0.z); qp[3] = pack2(q0.w, q0.w);
        qp[4] = pack2(q1.x, q1.x); qp[5] = pack2(q1.y, q1.y);
        qp[6] = pack2(q1.z, q1.z); qp[7] = pack2(q1.w, q1.w);
    }

    // exp2 poly constants (2^r, r in [-0.5, 0.5], degree 5 Taylor)
    const ull MAGIC2    = pack2(12582912.0f, 12582912.0f);    // 1.5 * 2^23
    const ull NEGMAGIC2 = pack2(-12582912.0f, -12582912.0f);
    const ull NEGONE2   = pack2(-1.0f, -1.0f);
    const ull K0 = pack2(1.0f, 1.0f);
    const ull K1 = pack2(0.69314718056f, 0.69314718056f);
    const ull K2 = pack2(0.240226506959f, 0.240226506959f);
    const ull K3 = pack2(0.0555041086648f, 0.0555041086648f);
    const ull K4 = pack2(0.00961812910763f, 0.00961812910763f);
    const ull K5 = pack2(0.00133335581464f, 0.00133335581464f);

    ull acc[4][4];
    #pragma unroll
    for (int i = 0; i < 4; i++)
        #pragma unroll
        for (int k = 0; k < 4; k++) acc[i][k] = 0ULL;
    ull l2 = 0ULL;

    const float* fTb = g_fT + (size_t)b * CQ * NN_;
    const float* hb  = g_h  + (size_t)b * NN_ * CC;

    for (int n0 = 0; n0 < NN_; n0 += TN) {
        // ---- tile loads ----
        if (t < 128) {
            int d = t >> 4, c4 = (t & 15) * 4;
            *(float4*)&f_s[d * TN + c4] =
                *(const float4*)&fTb[(size_t)d * NN_ + n0 + c4];
        }
        {
            const float4* hsrc = (const float4*)&hb[(size_t)n0 * CC];
            float4* hdst = (float4*)h_s;
            #pragma unroll
            for (int k = 0; k < 4; k++) hdst[t + k * THREADS] = hsrc[t + k * THREADS];
        }
        __syncthreads();

        // ---- stage A: scores + exp2 -> w_s ----
        #pragma unroll 2
        for (int j = 0; j < 16; j++) {
            int n = nh + 2 * j;
            ull s2 = mul2(qp[0], *(const ull*)&f_s[0 * TN + n]);
            #pragma unroll
            for (int d = 1; d < CQ; d++)
                s2 = ffma2(qp[d], *(const ull*)&f_s[d * TN + n], s2);
            // exp2: k = round(s), r = s - k, w = p(r) * 2^k
            ull t2 = add2(s2, MAGIC2);
            ull u2 = add2(t2, NEGMAGIC2);
            ull r2 = ffma2(u2, NEGONE2, s2);
            ull p2 = ffma2(K5, r2, K4);
            p2 = ffma2(p2, r2, K3);
            p2 = ffma2(p2, r2, K2);
            p2 = ffma2(p2, r2, K1);
            p2 = ffma2(p2, r2, K0);
            unsigned tlo = (unsigned)t2, thi = (unsigned)(t2 >> 32);
            float plo, phi; unpack2(p2, plo, phi);
            float wlo = __uint_as_float(__float_as_uint(plo) + (tlo << 23));
            float whi = __uint_as_float(__float_as_uint(phi) + (thi << 23));
            w_s[mloc * WROW + n]     = wlo;
            w_s[mloc * WROW + n + 1] = whi;
            l2 = add2(l2, pack2(wlo, whi));
        }
        __syncthreads();

        // ---- stage B: acc += w * h ----
        const float* wr = w_s + tmg * 4 * WROW;
        #pragma unroll 4
        for (int n = 0; n < TN; n++) {
            ull wp0 = pack2(wr[n], wr[n]);
            ull wp1 = pack2(wr[WROW + n], wr[WROW + n]);
            ull wp2 = pack2(wr[2 * WROW + n], wr[2 * WROW + n]);
            ull wp3 = pack2(wr[3 * WROW + n], wr[3 * WROW + n]);
            ulonglong2 hv0 = *(const ulonglong2*)&h_s[n * CC + tc * 4];
            ulonglong2 hv1 = *(const ulonglong2*)&h_s[n * CC + 32 + tc * 4];
            acc[0][0] = ffma2(hv0.x, wp0, acc[0][0]);
            acc[0][1] = ffma2(hv0.y, wp0, acc[0][1]);
            acc[0][2] = ffma2(hv1.x, wp0, acc[0][2]);
            acc[0][3] = ffma2(hv1.y, wp0, acc[0][3]);
            acc[1][0] = ffma2(hv0.x, wp1, acc[1][0]);
            acc[1][1] = ffma2(hv0.y, wp1, acc[1][1]);
            acc[1][2] = ffma2(hv1.x, wp1, acc[1][2]);
            acc[1][3] = ffma2(hv1.y, wp1, acc[1][3]);
            acc[2][0] = ffma2(hv0.x, wp2, acc[2][0]);
            acc[2][1] = ffma2(hv0.y, wp2, acc[2][1]);
            acc[2][2] = ffma2(hv1.x, wp2, acc[2][2]);
            acc[2][3] = ffma2(hv1.y, wp2, acc[2][3]);
            acc[3][0] = ffma2(hv0.x, wp3, acc[3][0]);
            acc[3][1] = ffma2(hv0.y, wp3, acc[3][1]);
            acc[3][2] = ffma2(hv1.x, wp3, acc[3][2]);
            acc[3][3] = ffma2(hv1.y, wp3, acc[3][3]);
        }
        __syncthreads();
    }

    // ---- l reduction: two partial sums per m ----
    {
        float lo, hi; unpack2(l2, lo, hi);
        float myl = lo + hi;
        if (t < 128) l_s[t] = myl;
        __syncthreads();
        if (t >= 128) l_s[t - 128] += myl;
        __syncthreads();
    }

    // ---- epilogue: out[c][m] = gamma/l * acc + x[c][m] ----
    float gm = gamma[0];
    float scale[4];
    #pragma unroll
    for (int i = 0; i < 4; i++) scale[i] = gm / l_s[tmg * 4 + i];

    const float* xb = x   + (size_t)b * CC * NN_;
    float*       ob = out + (size_t)b * CC * NN_;
    int mg = mt + tmg * 4;

    #pragma unroll
    for (int grp = 0; grp < 2; grp++) {
        #pragma unroll
        for (int q = 0; q < 4; q++) {
            int c = grp * 32 + tc * 4 + q;
            float v[4];
            #pragma unroll
            for (int i = 0; i < 4; i++) {
                float lo, hi; unpack2(acc[i][grp * 2 + (q >> 1)], lo, hi);
                v[i] = (q & 1) ? hi : lo;
            }
            float4 xv = *(const float4*)&xb[(size_t)c * NN_ + mg];
            float4 r;
            r.x = fmaf(v[0], scale[0], xv.x);
            r.y = fmaf(v[1], scale[1], xv.y);
            r.z = fmaf(v[2], scale[2], xv.z);
            r.w = fmaf(v[3], scale[3], xv.w);
            *(float4*)&ob[(size_t)c * NN_ + mg] = r;
        }
    }
}

// ============================================================================
extern "C" void kernel_launch(void* const* d_in, const int* in_sizes, int n_in,
                              void* d_out, int out_size)
{
    const float* x     = (const float*)d_in[0];
    const float* Wq    = (const float*)d_in[1];
    const float* bq    = (const float*)d_in[2];
    const float* Wk    = (const float*)d_in[3];
    const float* bk    = (const float*)d_in[4];
    const float* Wv    = (const float*)d_in[5];
    const float* bv    = (const float*)d_in[6];
    const float* gamma = (const float*)d_in[7];
    float* out = (float*)d_out;

    static bool attr_set = false;
    const int smem_bytes = (TM * WROW + TN * CC + CQ * TN + TM) * sizeof(float);
    if (!attr_set) {
        cudaFuncSetAttribute(attn_kernel,
                             cudaFuncAttributeMaxDynamicSharedMemorySize, smem_bytes);
        attr_set = true;
    }

    proj_kernel<<<BATCH * NN_ / 128, 128>>>(x, Wq, bq, Wk, bk, Wv, bv);
    attn_kernel<<<BATCH * NN_ / TM, THREADS, smem_bytes>>>(x, gamma, out);
}

// round 5
// speedup vs baseline: 4.6759x; 4.6759x over previous
#include <cuda_runtime.h>
#include <cstdint>

#define BATCH 8
#define CC    64
#define CQ    8
#define NN_   4096
#define TMC   128          // m-rows per CTA (4 warps x 32)
#define TN    64           // n-tile
#define NT    (NN_ / TN)
#define THREADS 128

typedef unsigned long long ull;

// Scratch (device globals; no allocation allowed)
__device__ float g_f [(size_t)BATCH * NN_ * CQ];   // keys  [B][N][8], pre-scaled log2e
__device__ float g_g [(size_t)BATCH * NN_ * CQ];   // query [B][N][8]
__device__ float g_hT[(size_t)BATCH * CC * NN_];   // values transposed [B][C][N]

// ---------------------------------------------------------------- helpers
__device__ __forceinline__ uint32_t smem_u32(const void* p) {
    uint32_t a;
    asm("{ .reg .u64 t; cvta.to.shared.u64 t, %1; cvt.u32.u64 %0, t; }"
        : "=r"(a) : "l"(p));
    return a;
}
#define CPA16(dst, src) \
    asm volatile("cp.async.cg.shared.global [%0], [%1], 16;" \
                 :: "r"(dst), "l"(__cvta_generic_to_global(src)))
#define CPCOMMIT() asm volatile("cp.async.commit_group;" ::: "memory")
#define CPWAIT0()  asm volatile("cp.async.wait_group 0;" ::: "memory")

__device__ __forceinline__ void ldsm4(uint32_t& r0, uint32_t& r1,
                                      uint32_t& r2, uint32_t& r3, uint32_t a) {
    asm volatile("ldmatrix.sync.aligned.m8n8.x4.shared.b16 {%0,%1,%2,%3}, [%4];"
                 : "=r"(r0), "=r"(r1), "=r"(r2), "=r"(r3) : "r"(a));
}
__device__ __forceinline__ void mma8(float* d, const uint32_t* a,
                                     uint32_t b0, uint32_t b1) {
    asm volatile("mma.sync.aligned.m16n8k8.row.col.f32.tf32.tf32.f32 "
                 "{%0,%1,%2,%3},{%4,%5,%6,%7},{%8,%9},{%0,%1,%2,%3};"
                 : "+f"(d[0]), "+f"(d[1]), "+f"(d[2]), "+f"(d[3])
                 : "r"(a[0]), "r"(a[1]), "r"(a[2]), "r"(a[3]), "r"(b0), "r"(b1));
}
#define STS64(addr, v) \
    asm volatile("st.shared.b64 [%0], %1;" :: "r"(addr), "l"(v) : "memory")

// ---- packed f32x2 ----
__device__ __forceinline__ ull pack2f(float a, float b) {
    ull r; asm("mov.b64 %0, {%1, %2};" : "=l"(r) : "f"(a), "f"(b)); return r;
}
__device__ __forceinline__ void unpack2f(ull v, float& a, float& b) {
    asm("mov.b64 {%0, %1}, %2;" : "=f"(a), "=f"(b) : "l"(v));
}
__device__ __forceinline__ ull ffma2(ull a, ull b, ull c) {
    ull d; asm("fma.rn.f32x2 %0, %1, %2, %3;" : "=l"(d) : "l"(a), "l"(b), "l"(c)); return d;
}
__device__ __forceinline__ ull add2(ull a, ull b) {
    ull d; asm("add.rn.f32x2 %0, %1, %2;" : "=l"(d) : "l"(a), "l"(b)); return d;
}
__device__ __forceinline__ ull exp2_pair(ull s2) {
    const ull MAGIC2    = pack2f(12582912.0f, 12582912.0f);
    const ull NEGMAGIC2 = pack2f(-12582912.0f, -12582912.0f);
    const ull NEGONE2   = pack2f(-1.0f, -1.0f);
    const ull K0 = pack2f(1.0f, 1.0f);
    const ull K1 = pack2f(0.69314718056f, 0.69314718056f);
    const ull K2 = pack2f(0.240226506959f, 0.240226506959f);
    const ull K3 = pack2f(0.0555041086648f, 0.0555041086648f);
    const ull K4 = pack2f(0.00961812910763f, 0.00961812910763f);
    const ull K5 = pack2f(0.00133335581464f, 0.00133335581464f);
    ull t2 = add2(s2, MAGIC2);
    ull kf = add2(t2, NEGMAGIC2);
    ull r2 = ffma2(kf, NEGONE2, s2);
    ull p2 = ffma2(K5, r2, K4);
    p2 = ffma2(p2, r2, K3);
    p2 = ffma2(p2, r2, K2);
    p2 = ffma2(p2, r2, K1);
    p2 = ffma2(p2, r2, K0);
    uint32_t tlo = (uint32_t)t2, thi = (uint32_t)(t2 >> 32);
    uint32_t plo = (uint32_t)p2, phi = (uint32_t)(p2 >> 32);
    return (ull)(plo + (tlo << 23)) | ((ull)(phi + (thi << 23)) << 32);
}

// ============================================================================
// Kernel 1: projections. x:[B,64,N] -> f:[B,N,8] (x log2e), g:[B,N,8], hT:[B,64,N]
// ============================================================================
__global__ __launch_bounds__(128) void proj_kernel(
    const float* __restrict__ x,
    const float* __restrict__ Wq, const float* __restrict__ bq,
    const float* __restrict__ Wk, const float* __restrict__ bk,
    const float* __restrict__ Wv, const float* __restrict__ bv)
{
    __shared__ float sWq[CQ * CC], sWk[CQ * CC], sWv[CC * CC];
    __shared__ float sbq[CQ], sbk[CQ], sbv[CC];
    int t = threadIdx.x;
    for (int i = t; i < CQ * CC; i += 128) { sWq[i] = Wq[i]; sWk[i] = Wk[i]; }
    for (int i = t; i < CC * CC; i += 128) sWv[i] = Wv[i];
    if (t < CQ) { sbq[t] = bq[t]; sbk[t] = bk[t]; }
    if (t < CC) sbv[t] = bv[t];
    __syncthreads();

    int b = blockIdx.x / (NN_ / 128);
    int n = (blockIdx.x % (NN_ / 128)) * 128 + t;

    float xv[CC];
    const float* xb = x + ((size_t)b * CC) * NN_ + n;
    #pragma unroll
    for (int c = 0; c < CC; c++) xv[c] = xb[(size_t)c * NN_];

    const float LOG2E = 1.4426950408889634f;
    size_t base = (size_t)b * NN_ + n;

    #pragma unroll 2
    for (int d = 0; d < CQ; d++) {
        float af = sbq[d], ag = sbk[d];
        #pragma unroll
        for (int c = 0; c < CC; c++) {
            af = fmaf(sWq[d * CC + c], xv[c], af);
            ag = fmaf(sWk[d * CC + c], xv[c], ag);
        }
        g_f[base * CQ + d] = af * LOG2E;   // keys, pre-scaled by log2e
        g_g[base * CQ + d] = ag;           // queries
    }
    #pragma unroll 4
    for (int o = 0; o < CC; o++) {
        float a = sbv[o];
        #pragma unroll
        for (int c = 0; c < CC; c++) a = fmaf(sWv[o * CC + c], xv[c], a);
        g_hT[((size_t)b * CC + o) * NN_ + n] = a;
    }
}

// ============================================================================
// Kernel 2: flash attention on mma.sync tf32 (m16n8k8).
//   CTA: 128 m (4 warps x 32m). Sweep 64-n tiles, cp.async double-buffered.
//   GEMM1: S[32m x 64n] = G x F^T (K=8). exp2 in regs. W -> warp-private smem.
//   GEMM2: O[32m x 64c] += W x H (K=64), accumulated in registers all sweep.
// ============================================================================
// smem byte offsets. H tile rows padded to 272B (68 f), F rows 48B (12 f),
// W rows 272B. All LDSM rows land on distinct 16B bank lanes.
#define HSTR   272
#define FSTR   48
#define OFF_H0 0
#define OFF_H1 17408
#define OFF_F0 34816
#define OFF_F1 37888
#define OFF_W  40960
#define WSZ    8704          // 32 * 272
#define SMEM_SZ (OFF_W + 4 * WSZ)   // 75776

__global__ __launch_bounds__(THREADS) void attn_kernel(
    const float* __restrict__ x,
    const float* __restrict__ gamma,
    float* __restrict__ out)
{
    extern __shared__ __align__(128) char smem[];
    uint32_t sb = smem_u32(smem);

    int t = threadIdx.x;
    int wid = t >> 5, lane = t & 31;
    int grp = lane >> 3, row8 = lane & 7;
    int b  = blockIdx.x >> 5;
    int mt = (blockIdx.x & 31) * TMC;
    int mw = mt + wid * 32;

    // LDSM per-lane base offsets
    uint32_t off_f = ((grp >> 1) * 8 + row8) * FSTR + (grp & 1) * 16;
    uint32_t off_h = ((grp >> 1) * 8 + row8) * HSTR + (grp & 1) * 16;
    uint32_t off_w = ((grp & 1) * 8 + row8) * HSTR + (grp >> 1) * 16;
    uint32_t wbase = sb + OFF_W + wid * WSZ;
    uint32_t wld   = wbase + off_w;
    uint32_t wst   = wbase + (lane >> 2) * HSTR + (lane & 3) * 8;

    // G fragments (A operand, K=8): a0=(r,k) a1=(r+8,k) a2=(r,k+4) a3=(r+8,k+4)
    uint32_t ga[2][4];
    {
        const float* gb = g_g + ((size_t)b * NN_) * CQ;
        int r = lane >> 2, k = lane & 3;
        #pragma unroll
        for (int m2 = 0; m2 < 2; m2++) {
            ga[m2][0] = __float_as_uint(gb[(size_t)(mw + m2 * 16 + r)     * CQ + k]);
            ga[m2][1] = __float_as_uint(gb[(size_t)(mw + m2 * 16 + r + 8) * CQ + k]);
            ga[m2][2] = __float_as_uint(gb[(size_t)(mw + m2 * 16 + r)     * CQ + k + 4]);
            ga[m2][3] = __float_as_uint(gb[(size_t)(mw + m2 * 16 + r + 8) * CQ + k + 4]);
        }
    }

    float acc[2][8][4];
    #pragma unroll
    for (int m2 = 0; m2 < 2; m2++)
        #pragma unroll
        for (int c = 0; c < 8; c++)
            #pragma unroll
            for (int i = 0; i < 4; i++) acc[m2][c][i] = 0.0f;
    ull l2[2][2] = {{0ULL, 0ULL}, {0ULL, 0ULL}};

    const float* hsrc0 = g_hT + (size_t)b * CC * NN_;
    const float* fsrc0 = g_f + (size_t)b * NN_ * CQ;

    // tile loader (cp.async)
    auto load_tile = [&](int it) {
        int n0 = it * TN;
        uint32_t hb = sb + ((it & 1) ? OFF_H1 : OFF_H0);
        uint32_t fb = sb + ((it & 1) ? OFF_F1 : OFF_F0);
        #pragma unroll
        for (int p = 0; p < 8; p++) {
            int cid = t + p * THREADS;
            int row = cid >> 4, col = (cid & 15) * 4;
            CPA16(hb + row * HSTR + col * 4, hsrc0 + (size_t)row * NN_ + n0 + col);
        }
        {
            int row = t >> 1, half = t & 1;
            CPA16(fb + row * FSTR + half * 16,
                  fsrc0 + (size_t)(n0 + row) * CQ + half * 4);
        }
        CPCOMMIT();
    };

    load_tile(0);

    for (int it = 0; it < NT; it++) {
        CPWAIT0();
        __syncthreads();
        if (it + 1 < NT) load_tile(it + 1);

        uint32_t hb = sb + ((it & 1) ? OFF_H1 : OFF_H0);
        uint32_t fb = sb + ((it & 1) ? OFF_F1 : OFF_F0);

        // ---- GEMM1: S = G x F^T ----
        float s[2][8][4];
        #pragma unroll
        for (int m2 = 0; m2 < 2; m2++)
            #pragma unroll
            for (int ns = 0; ns < 8; ns++)
                #pragma unroll
                for (int i = 0; i < 4; i++) s[m2][ns][i] = 0.0f;
        #pragma unroll
        for (int np = 0; np < 4; np++) {
            uint32_t b0, b1, b2, b3;
            ldsm4(b0, b1, b2, b3, fb + np * 16 * FSTR + off_f);
            mma8(s[0][2 * np],     ga[0], b0, b1);
            mma8(s[1][2 * np],     ga[1], b0, b1);
            mma8(s[0][2 * np + 1], ga[0], b2, b3);
            mma8(s[1][2 * np + 1], ga[1], b2, b3);
        }

        // ---- exp2 + W store (warp-private) ----
        #pragma unroll
        for (int m2 = 0; m2 < 2; m2++) {
            #pragma unroll
            for (int ns = 0; ns < 8; ns++) {
                ull w01 = exp2_pair(pack2f(s[m2][ns][0], s[m2][ns][1]));
                ull w23 = exp2_pair(pack2f(s[m2][ns][2], s[m2][ns][3]));
                l2[m2][0] = add2(l2[m2][0], w01);
                l2[m2][1] = add2(l2[m2][1], w23);
                uint32_t a = wst + m2 * 16 * HSTR + ns * 32;
                STS64(a, w01);
                STS64(a + 8 * HSTR, w23);
            }
        }
        __syncwarp();

        // ---- GEMM2: O += W x H ----
        #pragma unroll
        for (int ks = 0; ks < 8; ks++) {
            uint32_t a0[4], a1[4];
            ldsm4(a0[0], a0[1], a0[2], a0[3], wld + ks * 32);
            ldsm4(a1[0], a1[1], a1[2], a1[3], wld + 16 * HSTR + ks * 32);
            #pragma unroll
            for (int cp = 0; cp < 4; cp++) {
                uint32_t r0, r1, r2, r3;
                ldsm4(r0, r1, r2, r3, hb + off_h + cp * 16 * HSTR + ks * 32);
                mma8(acc[0][2 * cp],     a0, r0, r1);
                mma8(acc[1][2 * cp],     a1, r0, r1);
                mma8(acc[0][2 * cp + 1], a0, r2, r3);
                mma8(acc[1][2 * cp + 1], a1, r2, r3);
            }
        }
        __syncwarp();
    }

    // ---- l reduction (quad) + epilogue ----
    float gm = gamma[0];
    float scale[2][2];
    #pragma unroll
    for (int m2 = 0; m2 < 2; m2++) {
        #pragma unroll
        for (int rh = 0; rh < 2; rh++) {
            float lo, hi; unpack2f(l2[m2][rh], lo, hi);
            float l = lo + hi;
            l += __shfl_xor_sync(0xFFFFFFFF, l, 1);
            l += __shfl_xor_sync(0xFFFFFFFF, l, 2);
            scale[m2][rh] = gm / l;
        }
    }

    const float* xb = x   + (size_t)b * CC * NN_;
    float*       ob = out + (size_t)b * CC * NN_;
    int r = lane >> 2, q = lane & 3;
    #pragma unroll
    for (int m2 = 0; m2 < 2; m2++) {
        int m0 = mw + m2 * 16 + r;
        #pragma unroll
        for (int cs = 0; cs < 8; cs++) {
            int c = cs * 8 + 2 * q;
            size_t a00 = (size_t)c * NN_ + m0;
            size_t a01 = a00 + NN_;          // c+1
            ob[a00]     = fmaf(acc[m2][cs][0], scale[m2][0], xb[a00]);
            ob[a01]     = fmaf(acc[m2][cs][1], scale[m2][0], xb[a01]);
            ob[a00 + 8] = fmaf(acc[m2][cs][2], scale[m2][1], xb[a00 + 8]);
            ob[a01 + 8] = fmaf(acc[m2][cs][3], scale[m2][1], xb[a01 + 8]);
        }
    }
}

// ============================================================================
extern "C" void kernel_launch(void* const* d_in, const int* in_sizes, int n_in,
                              void* d_out, int out_size)
{
    const float* x     = (const float*)d_in[0];
    const float* Wq    = (const float*)d_in[1];
    const float* bq    = (const float*)d_in[2];
    const float* Wk    = (const float*)d_in[3];
    const float* bk    = (const float*)d_in[4];
    const float* Wv    = (const float*)d_in[5];
    const float* bv    = (const float*)d_in[6];
    const float* gamma = (const float*)d_in[7];
    float* out = (float*)d_out;

    static bool attr_set = false;
    if (!attr_set) {
        cudaFuncSetAttribute(attn_kernel,
                             cudaFuncAttributeMaxDynamicSharedMemorySize, SMEM_SZ);
        attr_set = true;
    }

    proj_kernel<<<BATCH * NN_ / 128, 128>>>(x, Wq, bq, Wk, bk, Wv, bv);
    attn_kernel<<<BATCH * NN_ / TMC, THREADS, SMEM_SZ>>>(x, gamma, out);
}

// round 6
// speedup vs baseline: 5.0499x; 1.0800x over previous
#include <cuda_runtime.h>
#include <cstdint>

#define BATCH 8
#define CC    64
#define CQ    8
#define NN_   4096
#define TMC   128          // m-rows per CTA (4 m-groups x 32)
#define TN    64           // n-tile
#define NT    (NN_ / TN)
#define THREADS 256

typedef unsigned long long ull;

// Scratch (device globals; no allocation allowed)
__device__ float g_f [(size_t)BATCH * NN_ * CQ];   // keys  [B][N][8], pre-scaled log2e
__device__ float g_g [(size_t)BATCH * NN_ * CQ];   // query [B][N][8]
__device__ float g_hT[(size_t)BATCH * CC * NN_];   // values transposed [B][C][N]

// ---------------------------------------------------------------- helpers
__device__ __forceinline__ uint32_t smem_u32(const void* p) {
    uint32_t a;
    asm("{ .reg .u64 t; cvta.to.shared.u64 t, %1; cvt.u32.u64 %0, t; }"
        : "=r"(a) : "l"(p));
    return a;
}
#define CPA16(dst, src) \
    asm volatile("cp.async.cg.shared.global [%0], [%1], 16;" \
                 :: "r"(dst), "l"(__cvta_generic_to_global(src)))
#define CPCOMMIT() asm volatile("cp.async.commit_group;" ::: "memory")
#define CPWAIT0()  asm volatile("cp.async.wait_group 0;" ::: "memory")

__device__ __forceinline__ void ldsm4(uint32_t& r0, uint32_t& r1,
                                      uint32_t& r2, uint32_t& r3, uint32_t a) {
    asm volatile("ldmatrix.sync.aligned.m8n8.x4.shared.b16 {%0,%1,%2,%3}, [%4];"
                 : "=r"(r0), "=r"(r1), "=r"(r2), "=r"(r3) : "r"(a));
}
__device__ __forceinline__ void mma8(float* d, const uint32_t* a,
                                     uint32_t b0, uint32_t b1) {
    asm volatile("mma.sync.aligned.m16n8k8.row.col.f32.tf32.tf32.f32 "
                 "{%0,%1,%2,%3},{%4,%5,%6,%7},{%8,%9},{%0,%1,%2,%3};"
                 : "+f"(d[0]), "+f"(d[1]), "+f"(d[2]), "+f"(d[3])
                 : "r"(a[0]), "r"(a[1]), "r"(a[2]), "r"(a[3]), "r"(b0), "r"(b1));
}
#define STS64(addr, v) \
    asm volatile("st.shared.b64 [%0], %1;" :: "r"(addr), "l"(v) : "memory")

// ---- packed f32x2 ----
__device__ __forceinline__ ull pack2f(float a, float b) {
    ull r; asm("mov.b64 %0, {%1, %2};" : "=l"(r) : "f"(a), "f"(b)); return r;
}
__device__ __forceinline__ void unpack2f(ull v, float& a, float& b) {
    asm("mov.b64 {%0, %1}, %2;" : "=f"(a), "=f"(b) : "l"(v));
}
__device__ __forceinline__ ull ffma2(ull a, ull b, ull c) {
    ull d; asm("fma.rn.f32x2 %0, %1, %2, %3;" : "=l"(d) : "l"(a), "l"(b), "l"(c)); return d;
}
__device__ __forceinline__ ull add2(ull a, ull b) {
    ull d; asm("add.rn.f32x2 %0, %1, %2;" : "=l"(d) : "l"(a), "l"(b)); return d;
}
__device__ __forceinline__ ull exp2_pair(ull s2) {
    const ull MAGIC2    = pack2f(12582912.0f, 12582912.0f);
    const ull NEGMAGIC2 = pack2f(-12582912.0f, -12582912.0f);
    const ull NEGONE2   = pack2f(-1.0f, -1.0f);
    const ull K0 = pack2f(1.0f, 1.0f);
    const ull K1 = pack2f(0.69314718056f, 0.69314718056f);
    const ull K2 = pack2f(0.240226506959f, 0.240226506959f);
    const ull K3 = pack2f(0.0555041086648f, 0.0555041086648f);
    const ull K4 = pack2f(0.00961812910763f, 0.00961812910763f);
    const ull K5 = pack2f(0.00133335581464f, 0.00133335581464f);
    ull t2 = add2(s2, MAGIC2);
    ull kf = add2(t2, NEGMAGIC2);
    ull r2 = ffma2(kf, NEGONE2, s2);
    ull p2 = ffma2(K5, r2, K4);
    p2 = ffma2(p2, r2, K3);
    p2 = ffma2(p2, r2, K2);
    p2 = ffma2(p2, r2, K1);
    p2 = ffma2(p2, r2, K0);
    uint32_t tlo = (uint32_t)t2, thi = (uint32_t)(t2 >> 32);
    uint32_t plo = (uint32_t)p2, phi = (uint32_t)(p2 >> 32);
    return (ull)(plo + (tlo << 23)) | ((ull)(phi + (thi << 23)) << 32);
}

// ============================================================================
// Kernel 1: projections. x:[B,64,N] -> f:[B,N,8] (x log2e), g:[B,N,8], hT:[B,64,N]
// ============================================================================
__global__ __launch_bounds__(128) void proj_kernel(
    const float* __restrict__ x,
    const float* __restrict__ Wq, const float* __restrict__ bq,
    const float* __restrict__ Wk, const float* __restrict__ bk,
    const float* __restrict__ Wv, const float* __restrict__ bv)
{
    __shared__ float sWq[CQ * CC], sWk[CQ * CC], sWv[CC * CC];
    __shared__ float sbq[CQ], sbk[CQ], sbv[CC];
    int t = threadIdx.x;
    for (int i = t; i < CQ * CC; i += 128) { sWq[i] = Wq[i]; sWk[i] = Wk[i]; }
    for (int i = t; i < CC * CC; i += 128) sWv[i] = Wv[i];
    if (t < CQ) { sbq[t] = bq[t]; sbk[t] = bk[t]; }
    if (t < CC) sbv[t] = bv[t];
    __syncthreads();

    int b = blockIdx.x / (NN_ / 128);
    int n = (blockIdx.x % (NN_ / 128)) * 128 + t;

    float xv[CC];
    const float* xb = x + ((size_t)b * CC) * NN_ + n;
    #pragma unroll
    for (int c = 0; c < CC; c++) xv[c] = xb[(size_t)c * NN_];

    const float LOG2E = 1.4426950408889634f;
    size_t base = (size_t)b * NN_ + n;

    #pragma unroll 2
    for (int d = 0; d < CQ; d++) {
        float af = sbq[d], ag = sbk[d];
        #pragma unroll
        for (int c = 0; c < CC; c++) {
            af = fmaf(sWq[d * CC + c], xv[c], af);
            ag = fmaf(sWk[d * CC + c], xv[c], ag);
        }
        g_f[base * CQ + d] = af * LOG2E;
        g_g[base * CQ + d] = ag;
    }
    #pragma unroll 4
    for (int o = 0; o < CC; o++) {
        float a = sbv[o];
        #pragma unroll
        for (int c = 0; c < CC; c++) a = fmaf(sWv[o * CC + c], xv[c], a);
        g_hT[((size_t)b * CC + o) * NN_ + n] = a;
    }
}

// ============================================================================
// Kernel 2: flash attention on mma.sync tf32, 8 warps (m-group x half split).
//   warp (g,h): GEMM1 computes S[32m x 32n] for n-half h -> exp2 -> W patch g;
//               GEMM2 computes O[32m x 32c] for c-half h reading full-k W.
// ============================================================================
#define HSTR   272
#define FSTR   48
#define OFF_H0 0
#define OFF_H1 17408
#define OFF_F0 34816
#define OFF_F1 37888
#define OFF_W  40960
#define WSZ    8704                  // 32 rows * 272
#define OFF_L  (OFF_W + 4 * WSZ)     // 75776: l partials [4 g][2 h][32 m]
#define SMEM_SZ (OFF_L + 1024)

__global__ __launch_bounds__(THREADS, 2) void attn_kernel(
    const float* __restrict__ x,
    const float* __restrict__ gamma,
    float* __restrict__ out)
{
    extern __shared__ __align__(128) char smem[];
    uint32_t sb = smem_u32(smem);
    float* l_s = (float*)(smem + OFF_L);

    int t = threadIdx.x;
    int wid = t >> 5, lane = t & 31;
    int g  = wid & 3;          // m-group (32 m-rows)
    int hf = wid >> 2;         // half index (n-half in GEMM1, c-half in GEMM2)
    int grp = lane >> 3, row8 = lane & 7;
    int b  = blockIdx.x >> 5;
    int mt = (blockIdx.x & 31) * TMC;
    int mw = mt + g * 32;

    // LDSM per-lane base offsets
    uint32_t off_f = ((grp >> 1) * 8 + row8) * FSTR + (grp & 1) * 16;
    uint32_t off_h = ((grp >> 1) * 8 + row8) * HSTR + (grp & 1) * 16;
    uint32_t off_w = ((grp & 1) * 8 + row8) * HSTR + (grp >> 1) * 16;
    uint32_t wbase = sb + OFF_W + g * WSZ;
    uint32_t wld   = wbase + off_w;
    uint32_t wst   = wbase + (lane >> 2) * HSTR + (lane & 3) * 8 + hf * 128;

    // G fragments (A operand, K=8)
    uint32_t ga[2][4];
    {
        const float* gb = g_g + ((size_t)b * NN_) * CQ;
        int r = lane >> 2, k = lane & 3;
        #pragma unroll
        for (int m2 = 0; m2 < 2; m2++) {
            ga[m2][0] = __float_as_uint(gb[(size_t)(mw + m2 * 16 + r)     * CQ + k]);
            ga[m2][1] = __float_as_uint(gb[(size_t)(mw + m2 * 16 + r + 8) * CQ + k]);
            ga[m2][2] = __float_as_uint(gb[(size_t)(mw + m2 * 16 + r)     * CQ + k + 4]);
            ga[m2][3] = __float_as_uint(gb[(size_t)(mw + m2 * 16 + r + 8) * CQ + k + 4]);
        }
    }

    float acc[2][4][4];
    #pragma unroll
    for (int m2 = 0; m2 < 2; m2++)
        #pragma unroll
        for (int c = 0; c < 4; c++)
            #pragma unroll
            for (int i = 0; i < 4; i++) acc[m2][c][i] = 0.0f;
    ull l2[2][2] = {{0ULL, 0ULL}, {0ULL, 0ULL}};

    const float* hsrc0 = g_hT + (size_t)b * CC * NN_;
    const float* fsrc0 = g_f + (size_t)b * NN_ * CQ;

    auto load_tile = [&](int it) {
        int n0 = it * TN;
        uint32_t hb = sb + ((it & 1) ? OFF_H1 : OFF_H0);
        uint32_t fb = sb + ((it & 1) ? OFF_F1 : OFF_F0);
        #pragma unroll
        for (int p = 0; p < 4; p++) {
            int cid = t + p * THREADS;
            int row = cid >> 4, col = (cid & 15) * 4;
            CPA16(hb + row * HSTR + col * 4, hsrc0 + (size_t)row * NN_ + n0 + col);
        }
        if (t < 128) {
            int row = t >> 1, half = t & 1;
            CPA16(fb + row * FSTR + half * 16,
                  fsrc0 + (size_t)(n0 + row) * CQ + half * 4);
        }
        CPCOMMIT();
    };

    load_tile(0);

    for (int it = 0; it < NT; it++) {
        CPWAIT0();
        __syncthreads();                       // tile ready + prev GEMM2 done (W reuse)
        if (it + 1 < NT) load_tile(it + 1);

        uint32_t hb = sb + ((it & 1) ? OFF_H1 : OFF_H0);
        uint32_t fb = sb + ((it & 1) ? OFF_F1 : OFF_F0);

        // ---- GEMM1: S[32m x 32n] for my n-half ----
        float s[2][4][4];
        #pragma unroll
        for (int m2 = 0; m2 < 2; m2++)
            #pragma unroll
            for (int ns = 0; ns < 4; ns++)
                #pragma unroll
                for (int i = 0; i < 4; i++) s[m2][ns][i] = 0.0f;
        #pragma unroll
        for (int np2 = 0; np2 < 2; np2++) {
            int np = hf * 2 + np2;
            uint32_t b0, b1, b2, b3;
            ldsm4(b0, b1, b2, b3, fb + np * 16 * FSTR + off_f);
            mma8(s[0][2 * np2],     ga[0], b0, b1);
            mma8(s[1][2 * np2],     ga[1], b0, b1);
            mma8(s[0][2 * np2 + 1], ga[0], b2, b3);
            mma8(s[1][2 * np2 + 1], ga[1], b2, b3);
        }

        // ---- exp2 + W store (columns hf*32 .. hf*32+31 of m-group patch) ----
        #pragma unroll
        for (int m2 = 0; m2 < 2; m2++) {
            #pragma unroll
            for (int ns = 0; ns < 4; ns++) {
                ull w01 = exp2_pair(pack2f(s[m2][ns][0], s[m2][ns][1]));
                ull w23 = exp2_pair(pack2f(s[m2][ns][2], s[m2][ns][3]));
                l2[m2][0] = add2(l2[m2][0], w01);
                l2[m2][1] = add2(l2[m2][1], w23);
                uint32_t a = wst + m2 * 16 * HSTR + ns * 32;
                STS64(a, w01);
                STS64(a + 8 * HSTR, w23);
            }
        }
        __syncthreads();                       // W visible to partner half

        // ---- GEMM2: O[32m x 32c] for my c-half, full k=64 ----
        #pragma unroll
        for (int ks = 0; ks < 8; ks++) {
            uint32_t a0[4], a1[4];
            ldsm4(a0[0], a0[1], a0[2], a0[3], wld + ks * 32);
            ldsm4(a1[0], a1[1], a1[2], a1[3], wld + 16 * HSTR + ks * 32);
            #pragma unroll
            for (int cp2 = 0; cp2 < 2; cp2++) {
                int cp = hf * 2 + cp2;
                uint32_t r0, r1, r2, r3;
                ldsm4(r0, r1, r2, r3, hb + off_h + cp * 16 * HSTR + ks * 32);
                mma8(acc[0][2 * cp2],     a0, r0, r1);
                mma8(acc[1][2 * cp2],     a1, r0, r1);
                mma8(acc[0][2 * cp2 + 1], a0, r2, r3);
                mma8(acc[1][2 * cp2 + 1], a1, r2, r3);
            }
        }
    }

    // ---- l reduction: quad shuffle, cross-half via smem ----
    {
        int r = lane >> 2;
        #pragma unroll
        for (int m2 = 0; m2 < 2; m2++) {
            #pragma unroll
            for (int rh = 0; rh < 2; rh++) {
                float lo, hi; unpack2f(l2[m2][rh], lo, hi);
                float l = lo + hi;
                l += __shfl_xor_sync(0xFFFFFFFF, l, 1);
                l += __shfl_xor_sync(0xFFFFFFFF, l, 2);
                if ((lane & 3) == 0)
                    l_s[(g * 2 + hf) * 32 + m2 * 16 + rh * 8 + r] = l;
            }
        }
    }
    __syncthreads();

    float gm = gamma[0];
    float scale[2][2];
    {
        int r = lane >> 2;
        #pragma unroll
        for (int m2 = 0; m2 < 2; m2++)
            #pragma unroll
            for (int rh = 0; rh < 2; rh++) {
                int row = m2 * 16 + rh * 8 + r;
                scale[m2][rh] = gm / (l_s[(g * 2) * 32 + row] +
                                      l_s[(g * 2 + 1) * 32 + row]);
            }
    }

    const float* xb = x   + (size_t)b * CC * NN_;
    float*       ob = out + (size_t)b * CC * NN_;
    int r = lane >> 2, q = lane & 3;
    #pragma unroll
    for (int m2 = 0; m2 < 2; m2++) {
        int m0 = mw + m2 * 16 + r;
        #pragma unroll
        for (int cs = 0; cs < 4; cs++) {
            int c = hf * 32 + cs * 8 + 2 * q;
            size_t a00 = (size_t)c * NN_ + m0;
            size_t a01 = a00 + NN_;
            ob[a00]     = fmaf(acc[m2][cs][0], scale[m2][0], xb[a00]);
            ob[a01]     = fmaf(acc[m2][cs][1], scale[m2][0], xb[a01]);
            ob[a00 + 8] = fmaf(acc[m2][cs][2], scale[m2][1], xb[a00 + 8]);
            ob[a01 + 8] = fmaf(acc[m2][cs][3], scale[m2][1], xb[a01 + 8]);
        }
    }
}

// ============================================================================
extern "C" void kernel_launch(void* const* d_in, const int* in_sizes, int n_in,
                              void* d_out, int out_size)
{
    const float* x     = (const float*)d_in[0];
    const float* Wq    = (const float*)d_in[1];
    const float* bq    = (const float*)d_in[2];
    const float* Wk    = (const float*)d_in[3];
    const float* bk    = (const float*)d_in[4];
    const float* Wv    = (const float*)d_in[5];
    const float* bv    = (const float*)d_in[6];
    const float* gamma = (const float*)d_in[7];
    float* out = (float*)d_out;

    static bool attr_set = false;
    if (!attr_set) {
        cudaFuncSetAttribute(attn_kernel,
                             cudaFuncAttributeMaxDynamicSharedMemorySize, SMEM_SZ);
        attr_set = true;
    }

    proj_kernel<<<BATCH * NN_ / 128, 128>>>(x, Wq, bq, Wk, bk, Wv, bv);
    attn_kernel<<<BATCH * NN_ / TMC, THREADS, SMEM_SZ>>>(x, gamma, out);
}